// round 7
// baseline (speedup 1.0000x reference)
#include <cuda_runtime.h>
#include <cuda_bf16.h>
#include <cstdint>

// ---------------------------------------------------------------------------
// Scratch for per-token segment ranges (T = 132096 here; headroom).
#define MAX_T 140000
__device__ int g_seg_start[MAX_T];
__device__ int g_seg_end[MAX_T];

// Segments of one token are contiguous in seg_token_idx (built by
// repeat(token_rank, segs_per_token)); token ids are NOT sorted.
__global__ void seg_bounds_kernel(const int* __restrict__ idx, int S) {
    int i = blockIdx.x * blockDim.x + threadIdx.x;
    if (i >= S) return;
    int t = idx[i];
    if (i == 0 || idx[i - 1] != t) g_seg_start[t] = i;
    if (i == S - 1 || idx[i + 1] != t) g_seg_end[t] = i + 1;
}

// ---------------------------------------------------------------------------
__device__ __forceinline__ uint32_t smem_to_u32(const void* p) {
    uint32_t a;
    asm("{ .reg .u64 t; cvta.to.shared.u64 t, %1; cvt.u32.u64 %0, t; }"
        : "=r"(a) : "l"(p));
    return a;
}
__device__ __forceinline__ void ldsm_x4(uint32_t* r, uint32_t addr) {
    asm volatile("ldmatrix.sync.aligned.m8n8.x4.shared.b16 {%0,%1,%2,%3}, [%4];"
                 : "=r"(r[0]), "=r"(r[1]), "=r"(r[2]), "=r"(r[3]) : "r"(addr));
}
__device__ __forceinline__ void ldsm_x2(uint32_t& r0, uint32_t& r1, uint32_t addr) {
    asm volatile("ldmatrix.sync.aligned.m8n8.x2.shared.b16 {%0,%1}, [%2];"
                 : "=r"(r0), "=r"(r1) : "r"(addr));
}
__device__ __forceinline__ void hmma16816(float& c0, float& c1, float& c2, float& c3,
                                          uint32_t a0, uint32_t a1, uint32_t a2, uint32_t a3,
                                          uint32_t b0, uint32_t b1) {
    asm volatile(
        "mma.sync.aligned.m16n8k16.row.col.f32.bf16.bf16.f32 "
        "{%0,%1,%2,%3}, {%4,%5,%6,%7}, {%8,%9}, {%0,%1,%2,%3};"
        : "+f"(c0), "+f"(c1), "+f"(c2), "+f"(c3)
        : "r"(a0), "r"(a1), "r"(a2), "r"(a3), "r"(b0), "r"(b1));
}

// ---------------------------------------------------------------------------
// Split-bf16 GEMM with deduplicated fragments:
//   tok = th + tl, W = wh + wl;  out = th*wh + th*wl + tl*wh  (drop tl*wl).
// Token tile k-layout [0:32)=th, [32:64)=tl; W tile [0:32)=wh, [32:64)=wl.
// The 3 products reuse the same A/B fragments -> 4 ldsm + 6 MMA per (m, nt).
//
// Each 128-token tile is handled by a PAIR of 256-thread CTAs (H halves of
// 256 cols each) -> 72KB smem + <=128 regs -> 2 CTAs/SM, decoupled pipelines.
//
// smem rows 72 bf16 = 144 B (36 words): 8-row ldmatrix sets are conflict-free.
static constexpr int TILE_TOK = 128;
static constexpr int ROWB     = 144;                 // bytes per k-row
static constexpr int H_CTA    = 256;                 // H columns per CTA
static constexpr int SW_OFF   = 0;                   // W-split: 256 rows
static constexpr int ST0      = H_CTA * ROWB;        // 36864
static constexpr int TBYTES   = TILE_TOK * ROWB;     // 18432
static constexpr int ST1      = ST0 + TBYTES;        // 55296
static constexpr int SMEM_TOTAL = ST1 + TBYTES;      // 73728

#define NTHREADS 256    // 8 warps: each warp owns a 32-wide H slice

__global__ __launch_bounds__(NTHREADS, 2) void fused_hmma_kernel(
    const float* __restrict__ features,   // [S, 32]
    const float* __restrict__ W,          // [32, 512]
    const float* __restrict__ b,          // [512]
    float* __restrict__ out,              // [T, 512]
    int T, int ntiles)
{
    extern __shared__ char smem[];
    const uint32_t smem_base = smem_to_u32(smem);
    const int tid  = threadIdx.x;
    const int wid  = tid >> 5;            // 0..7
    const int lane = tid & 31;
    const int hbase = (blockIdx.x & 1) * H_CTA;   // this CTA's H half

    // --- Stage this half's W^T split into smem [hl=256][k=64] (once) ---
    for (int idx = tid; idx < 32 * H_CTA; idx += NTHREADS) {
        const int f = idx >> 8, hl = idx & (H_CTA - 1);   // coalesced over h
        const float wv = W[f * 512 + hbase + hl];
        const __nv_bfloat16 hb = __float2bfloat16(wv);
        const __nv_bfloat16 lb = __float2bfloat16(wv - __bfloat162float(hb));
        char* row = smem + SW_OFF + hl * ROWB;
        *(__nv_bfloat16*)(row + 2 * f)        = hb;  // wh
        *(__nv_bfloat16*)(row + 2 * (32 + f)) = lb;  // wl
    }
    __syncthreads();

    // --- Hoist this warp's W fragments (persistent registers) ---
    // Warp w owns local h-slice [w*32, w*32+32): 4 n-tiles x 4 k-steps x 2.
    const int wsl = wid * 32;
    uint32_t breg[4][4][2];
    {
        const uint32_t wb = smem_base + SW_OFF;
        #pragma unroll
        for (int nt = 0; nt < 4; nt++)
            #pragma unroll
            for (int ks = 0; ks < 4; ks++) {
                uint32_t addr = wb + (wsl + nt * 8 + (lane & 7)) * ROWB
                              + (ks * 16 + ((lane >> 3) & 1) * 8) * 2;
                ldsm_x2(breg[nt][ks][0], breg[nt][ks][1], addr);
            }
    }
    // Bias per n-tile: cols (lane&3)*2, +1 (rows r and r+8 share cols).
    float biasx[4], biasy[4];
    #pragma unroll
    for (int nt = 0; nt < 4; nt++) {
        const int col = hbase + wsl + nt * 8 + (lane & 3) * 2;
        biasx[nt] = b[col];
        biasy[nt] = b[col + 1];
    }

    const int step = gridDim.x >> 1;     // tile stride (grid is even)
    int tile = blockIdx.x >> 1;
    if (tile >= ntiles) return;          // defensive; grid is clamped

    // --- Gather: thread (f = lane, token row base = wid) ---
    const int f = lane, trow = wid;
    float ts[16];
    auto gather = [&](int tile_) {
        const int tok0 = tile_ * TILE_TOK;
        #pragma unroll
        for (int j = 0; j < 16; j++) {
            const int tok = tok0 + trow + 8 * j;
            int s0 = 0, n = 0;
            if (tok < T) { s0 = g_seg_start[tok]; n = g_seg_end[tok] - s0; }
            const float* p = features + (size_t)s0 * 32 + f;
            float a0 = (n > 0) ? p[0]  : 0.0f;
            float a1 = (n > 1) ? p[32] : 0.0f;
            float a2 = (n > 2) ? p[64] : 0.0f;
            float ex = 0.0f;
            for (int si = 3; si < n; si++) ex += p[32 * si];
            ts[j] = 1e-10f + ((a0 + a1) + (a2 + ex));
        }
    };
    auto convert_sts = [&](char* B) {
        #pragma unroll
        for (int j = 0; j < 16; j++) {
            const int r = trow + 8 * j;
            const __nv_bfloat16 hb = __float2bfloat16(ts[j]);
            const __nv_bfloat16 lb =
                __float2bfloat16(ts[j] - __bfloat162float(hb));
            char* row = B + r * ROWB;
            *(__nv_bfloat16*)(row + 2 * f)        = hb;  // th
            *(__nv_bfloat16*)(row + 2 * (32 + f)) = lb;  // tl
        }
    };

    // Prime the pipeline.
    gather(tile);
    convert_sts(smem + ST0);
    __syncthreads();

    int buf = 0;
    while (true) {
        const int next = tile + step;
        const bool has_next = next < ntiles;

        // Prefetch next tile's gather LDGs (consumed after the MMA phase).
        if (has_next) gather(next);

        // --- MMA + store phase on current buffer ---
        const uint32_t cur = smem_base + (buf ? ST1 : ST0);
        const int tok0 = tile * TILE_TOK;
        const uint32_t arow0 = cur + (lane & 15) * ROWB + ((lane >> 4) * 8) * 2;

        #pragma unroll 1
        for (int m = 0; m < 8; m++) {
            uint32_t a[4][4];                       // ks: th0, th1, tl0, tl1
            const uint32_t arow = arow0 + m * 16 * ROWB;
            #pragma unroll
            for (int ks = 0; ks < 4; ks++) ldsm_x4(a[ks], arow + ks * 32);

            const int r0 = tok0 + m * 16 + (lane >> 2);
            float2* o0 = reinterpret_cast<float2*>(
                out + (size_t)r0 * 512 + hbase + wsl + (lane & 3) * 2);
            float2* o1 = reinterpret_cast<float2*>(
                out + (size_t)(r0 + 8) * 512 + hbase + wsl + (lane & 3) * 2);
            const bool p0 = r0 < T, p1 = (r0 + 8) < T;

            #pragma unroll
            for (int nt = 0; nt < 4; nt++) {
                float c0 = biasx[nt], c1 = biasy[nt], c2 = c0, c3 = c1;
                // th * wh   (k = 0:32)
                hmma16816(c0, c1, c2, c3, a[0][0], a[0][1], a[0][2], a[0][3],
                          breg[nt][0][0], breg[nt][0][1]);
                hmma16816(c0, c1, c2, c3, a[1][0], a[1][1], a[1][2], a[1][3],
                          breg[nt][1][0], breg[nt][1][1]);
                // th * wl
                hmma16816(c0, c1, c2, c3, a[0][0], a[0][1], a[0][2], a[0][3],
                          breg[nt][2][0], breg[nt][2][1]);
                hmma16816(c0, c1, c2, c3, a[1][0], a[1][1], a[1][2], a[1][3],
                          breg[nt][3][0], breg[nt][3][1]);
                // tl * wh
                hmma16816(c0, c1, c2, c3, a[2][0], a[2][1], a[2][2], a[2][3],
                          breg[nt][0][0], breg[nt][0][1]);
                hmma16816(c0, c1, c2, c3, a[3][0], a[3][1], a[3][2], a[3][3],
                          breg[nt][1][0], breg[nt][1][1]);
                if (p0) o0[nt * 4] = make_float2(c0, c1);
                if (p1) o1[nt * 4] = make_float2(c2, c3);
            }
        }

        // Write next tile's token buffer; one sync per tile.
        if (has_next) convert_sts(smem + (buf ? ST0 : ST1));
        __syncthreads();
        if (!has_next) break;
        tile = next;
        buf ^= 1;
    }
}

// ---------------------------------------------------------------------------
extern "C" void kernel_launch(void* const* d_in, const int* in_sizes, int n_in,
                              void* d_out, int out_size) {
    const float* features = (const float*)d_in[0];   // [S, 32]
    const float* W        = (const float*)d_in[1];   // [32, 512]
    const float* b        = (const float*)d_in[2];   // [512]
    const int*   idx      = (const int*)d_in[3];     // [S]
    float*       out      = (float*)d_out;           // [T, 512]

    const int S = in_sizes[3];
    const int T = out_size / 512;
    const int ntiles = (T + TILE_TOK - 1) / TILE_TOK;

    static int nsm = 0;
    if (nsm == 0) {
        // First call is the (non-captured) correctness run; cached afterwards.
        cudaDeviceGetAttribute(&nsm, cudaDevAttrMultiProcessorCount, 0);
        if (nsm <= 0) nsm = 148;
        cudaFuncSetAttribute(fused_hmma_kernel,
                             cudaFuncAttributeMaxDynamicSharedMemorySize,
                             SMEM_TOTAL);
    }

    seg_bounds_kernel<<<(S + 255) / 256, 256>>>(idx, S);

    int half = nsm;
    if (half > ntiles) half = ntiles;
    fused_hmma_kernel<<<2 * half, NTHREADS, SMEM_TOTAL>>>(
        features, W, b, out, T, ntiles);
}

// round 8
// speedup vs baseline: 1.4088x; 1.4088x over previous
#include <cuda_runtime.h>
#include <cuda_bf16.h>
#include <cstdint>

// ---------------------------------------------------------------------------
// Scratch for per-token segment ranges (T = 132096 here; headroom).
#define MAX_T 140000
__device__ int g_seg_start[MAX_T];
__device__ int g_seg_end[MAX_T];

// Segments of one token are contiguous in seg_token_idx (built by
// repeat(token_rank, segs_per_token)); token ids are NOT sorted.
__global__ void seg_bounds_kernel(const int* __restrict__ idx, int S) {
    int i = blockIdx.x * blockDim.x + threadIdx.x;
    if (i >= S) return;
    int t = idx[i];
    if (i == 0 || idx[i - 1] != t) g_seg_start[t] = i;
    if (i == S - 1 || idx[i + 1] != t) g_seg_end[t] = i + 1;
}

// ---------------------------------------------------------------------------
__device__ __forceinline__ uint32_t smem_to_u32(const void* p) {
    uint32_t a;
    asm("{ .reg .u64 t; cvta.to.shared.u64 t, %1; cvt.u32.u64 %0, t; }"
        : "=r"(a) : "l"(p));
    return a;
}
__device__ __forceinline__ void ldsm_x4(uint32_t* r, uint32_t addr) {
    asm volatile("ldmatrix.sync.aligned.m8n8.x4.shared.b16 {%0,%1,%2,%3}, [%4];"
                 : "=r"(r[0]), "=r"(r[1]), "=r"(r[2]), "=r"(r[3]) : "r"(addr));
}
__device__ __forceinline__ void ldsm_x2(uint32_t& r0, uint32_t& r1, uint32_t addr) {
    asm volatile("ldmatrix.sync.aligned.m8n8.x2.shared.b16 {%0,%1}, [%2];"
                 : "=r"(r0), "=r"(r1) : "r"(addr));
}
__device__ __forceinline__ void hmma16816(float& c0, float& c1, float& c2, float& c3,
                                          uint32_t a0, uint32_t a1, uint32_t a2, uint32_t a3,
                                          uint32_t b0, uint32_t b1) {
    asm volatile(
        "mma.sync.aligned.m16n8k16.row.col.f32.bf16.bf16.f32 "
        "{%0,%1,%2,%3}, {%4,%5,%6,%7}, {%8,%9}, {%0,%1,%2,%3};"
        : "+f"(c0), "+f"(c1), "+f"(c2), "+f"(c3)
        : "r"(a0), "r"(a1), "r"(a2), "r"(a3), "r"(b0), "r"(b1));
}

// ---------------------------------------------------------------------------
// Split-bf16 GEMM with deduplicated fragments:
//   tok = th + tl, W = wh + wl;  out = th*wh + th*wl + tl*wh  (drop tl*wl).
// Token tile k-layout [0:32)=th, [32:64)=tl; W tile [0:32)=wh, [32:64)=wl.
// 4 ldsm-A + 6 MMA per (m, n-tile-pair-half) reusing fragments.
//
// Column pairing: within each 16-col H group, n-tile "e" covers physical cols
// {4q, 4q+1} and n-tile "o" covers {4q+2, 4q+3} (q = lane&3), so a thread's
// four accumulators per row are CONSECUTIVE output cols -> STG.128.
// W staging permutes rows accordingly: phys col p -> smem row
//   group*16 + ((p>>1)&1)*8 + 2*(p>>2) + (p&1).
//
// smem rows 72 bf16 = 144 B (36 words): 8-row ldmatrix sets conflict-free.
static constexpr int TILE_TOK = 128;
static constexpr int ROWB     = 144;                 // bytes per k-row
static constexpr int SW_OFF   = 0;                   // W-split: 512 rows
static constexpr int ST0      = 512 * ROWB;          // 73728
static constexpr int TBYTES   = TILE_TOK * ROWB;     // 18432
static constexpr int ST1      = ST0 + TBYTES;        // 92160
static constexpr int SMEM_TOTAL = ST1 + TBYTES;      // 110592

#define NTHREADS 512    // 16 warps: each warp owns a 32-wide H slice (2 pairs)

__global__ __launch_bounds__(NTHREADS, 1) void fused_hmma_kernel(
    const float* __restrict__ features,   // [S, 32]
    const float* __restrict__ W,          // [32, 512]
    const float* __restrict__ b,          // [512]
    float* __restrict__ out,              // [T, 512]
    int T, int ntiles)
{
    extern __shared__ char smem[];
    const uint32_t smem_base = smem_to_u32(smem);
    const int tid  = threadIdx.x;
    const int wid  = tid >> 5;            // 0..15
    const int lane = tid & 31;

    // --- Stage W^T split into smem with column-pair permutation (once) ---
    for (int idx = tid; idx < 32 * 512; idx += NTHREADS) {
        const int f = idx >> 9, h = idx & 511;       // coalesced LDG over h
        const float wv = W[idx];
        const __nv_bfloat16 hb = __float2bfloat16(wv);
        const __nv_bfloat16 lb = __float2bfloat16(wv - __bfloat162float(hb));
        const int g = h >> 4, p = h & 15;
        const int row = g * 16 + ((p >> 1) & 1) * 8 + 2 * (p >> 2) + (p & 1);
        char* r = smem + SW_OFF + row * ROWB;
        *(__nv_bfloat16*)(r + 2 * f)        = hb;    // wh  (k = f)
        *(__nv_bfloat16*)(r + 2 * (32 + f)) = lb;    // wl  (k = 32+f)
    }
    __syncthreads();

    // --- Hoist W fragments: 2 pairs x 2 tiles (e/o) x 4 k-steps x 2 regs ---
    const int wsl = wid * 32;             // global H base of this warp
    uint32_t breg[2][2][4][2];
    {
        const uint32_t wb = smem_base + SW_OFF;
        #pragma unroll
        for (int pr = 0; pr < 2; pr++)
            #pragma unroll
            for (int eo = 0; eo < 2; eo++)
                #pragma unroll
                for (int ks = 0; ks < 4; ks++) {
                    uint32_t addr = wb
                        + (wsl + pr * 16 + eo * 8 + (lane & 7)) * ROWB
                        + (ks * 16 + ((lane >> 3) & 1) * 8) * 2;
                    ldsm_x2(breg[pr][eo][ks][0], breg[pr][eo][ks][1], addr);
                }
    }
    // Bias: per pair, thread's 4 consecutive cols.
    const int q = lane & 3;
    float4 bias4[2];
    #pragma unroll
    for (int pr = 0; pr < 2; pr++)
        bias4[pr] = *reinterpret_cast<const float4*>(b + wsl + pr * 16 + 4 * q);

    int tile = blockIdx.x;
    if (tile >= ntiles) return;   // grid is clamped; defensive (uniform per CTA)

    // --- Gather: thread (f = lane, token row base = wid) ---
    const int f = lane, trow = wid;
    float ts[8];
    auto gather = [&](int tile_) {
        const int tok0 = tile_ * TILE_TOK;
        #pragma unroll
        for (int j = 0; j < 8; j++) {
            const int tok = tok0 + trow + 16 * j;
            int s0 = 0, n = 0;
            if (tok < T) { s0 = g_seg_start[tok]; n = g_seg_end[tok] - s0; }
            const float* p = features + (size_t)s0 * 32 + f;
            float a0 = (n > 0) ? p[0]  : 0.0f;
            float a1 = (n > 1) ? p[32] : 0.0f;
            float a2 = (n > 2) ? p[64] : 0.0f;
            float ex = 0.0f;
            for (int si = 3; si < n; si++) ex += p[32 * si];
            ts[j] = 1e-10f + ((a0 + a1) + (a2 + ex));
        }
    };
    auto convert_sts = [&](char* B) {
        #pragma unroll
        for (int j = 0; j < 8; j++) {
            const int r = trow + 16 * j;
            const __nv_bfloat16 hb = __float2bfloat16(ts[j]);
            const __nv_bfloat16 lb =
                __float2bfloat16(ts[j] - __bfloat162float(hb));
            char* row = B + r * ROWB;
            *(__nv_bfloat16*)(row + 2 * f)        = hb;  // th (k = f)
            *(__nv_bfloat16*)(row + 2 * (32 + f)) = lb;  // tl (k = 32+f)
        }
    };

    // Prime the pipeline.
    gather(tile);
    convert_sts(smem + ST0);
    __syncthreads();

    int buf = 0;
    while (true) {
        const int next = tile + gridDim.x;
        const bool has_next = next < ntiles;

        // Prefetch next tile's gather LDGs (consumed after the MMA phase).
        if (has_next) gather(next);

        // --- MMA + store phase on current buffer ---
        const uint32_t cur = smem_base + (buf ? ST1 : ST0);
        const int tok0 = tile * TILE_TOK;
        const uint32_t arow0 = cur + (lane & 15) * ROWB + ((lane >> 4) * 8) * 2;

        #pragma unroll 1
        for (int m = 0; m < 8; m++) {
            uint32_t a[4][4];                      // ks: th0, th1, tl0, tl1
            const uint32_t arow = arow0 + m * 16 * ROWB;
            #pragma unroll
            for (int ks = 0; ks < 4; ks++) ldsm_x4(a[ks], arow + ks * 32);

            const int r0 = tok0 + m * 16 + (lane >> 2);
            const bool p0 = r0 < T, p1 = (r0 + 8) < T;

            #pragma unroll
            for (int pr = 0; pr < 2; pr++) {
                float e0 = bias4[pr].x, e1 = bias4[pr].y, e2 = e0, e3 = e1;
                float o0 = bias4[pr].z, o1 = bias4[pr].w, o2 = o0, o3 = o1;
                #pragma unroll
                for (int eo = 0; eo < 2; eo++) {
                    float &c0 = eo ? o0 : e0, &c1 = eo ? o1 : e1;
                    float &c2 = eo ? o2 : e2, &c3 = eo ? o3 : e3;
                    // th * wh
                    hmma16816(c0, c1, c2, c3, a[0][0], a[0][1], a[0][2], a[0][3],
                              breg[pr][eo][0][0], breg[pr][eo][0][1]);
                    hmma16816(c0, c1, c2, c3, a[1][0], a[1][1], a[1][2], a[1][3],
                              breg[pr][eo][1][0], breg[pr][eo][1][1]);
                    // th * wl
                    hmma16816(c0, c1, c2, c3, a[0][0], a[0][1], a[0][2], a[0][3],
                              breg[pr][eo][2][0], breg[pr][eo][2][1]);
                    hmma16816(c0, c1, c2, c3, a[1][0], a[1][1], a[1][2], a[1][3],
                              breg[pr][eo][3][0], breg[pr][eo][3][1]);
                    // tl * wh
                    hmma16816(c0, c1, c2, c3, a[2][0], a[2][1], a[2][2], a[2][3],
                              breg[pr][eo][0][0], breg[pr][eo][0][1]);
                    hmma16816(c0, c1, c2, c3, a[3][0], a[3][1], a[3][2], a[3][3],
                              breg[pr][eo][1][0], breg[pr][eo][1][1]);
                }
                // 4 consecutive cols -> one STG.128 per row.
                float* o = out + (size_t)r0 * 512 + wsl + pr * 16 + 4 * q;
                if (p0) *reinterpret_cast<float4*>(o) =
                    make_float4(e0, e1, o0, o1);
                if (p1) *reinterpret_cast<float4*>(o + 8 * 512) =
                    make_float4(e2, e3, o2, o3);
            }
        }

        // Write next tile's token buffer; one sync per tile.
        if (has_next) convert_sts(smem + (buf ? ST0 : ST1));
        __syncthreads();
        if (!has_next) break;
        tile = next;
        buf ^= 1;
    }
}

// ---------------------------------------------------------------------------
extern "C" void kernel_launch(void* const* d_in, const int* in_sizes, int n_in,
                              void* d_out, int out_size) {
    const float* features = (const float*)d_in[0];   // [S, 32]
    const float* W        = (const float*)d_in[1];   // [32, 512]
    const float* b        = (const float*)d_in[2];   // [512]
    const int*   idx      = (const int*)d_in[3];     // [S]
    float*       out      = (float*)d_out;           // [T, 512]

    const int S = in_sizes[3];
    const int T = out_size / 512;
    const int ntiles = (T + TILE_TOK - 1) / TILE_TOK;

    static int nsm = 0;
    if (nsm == 0) {
        // First call is the (non-captured) correctness run; cached afterwards.
        cudaDeviceGetAttribute(&nsm, cudaDevAttrMultiProcessorCount, 0);
        if (nsm <= 0) nsm = 148;
        cudaFuncSetAttribute(fused_hmma_kernel,
                             cudaFuncAttributeMaxDynamicSharedMemorySize,
                             SMEM_TOTAL);
    }

    seg_bounds_kernel<<<(S + 255) / 256, 256>>>(idx, S);

    int grid = nsm;
    if (grid > ntiles) grid = ntiles;
    fused_hmma_kernel<<<grid, NTHREADS, SMEM_TOTAL>>>(
        features, W, b, out, T, ntiles);
}

// round 9
// speedup vs baseline: 1.7358x; 1.2321x over previous
#include <cuda_runtime.h>
#include <cuda_bf16.h>
#include <cstdint>

// ---------------------------------------------------------------------------
// Scratch for per-token segment ranges (T = 132096 here; headroom).
#define MAX_T 140000
__device__ int g_seg_start[MAX_T];
__device__ int g_seg_end[MAX_T];

// Segments of one token are contiguous in seg_token_idx (built by
// repeat(token_rank, segs_per_token)); token ids are NOT sorted.
__global__ void seg_bounds_kernel(const int* __restrict__ idx, int S) {
    int i = blockIdx.x * blockDim.x + threadIdx.x;
    if (i >= S) return;
    int t = idx[i];
    if (i == 0 || idx[i - 1] != t) g_seg_start[t] = i;
    if (i == S - 1 || idx[i + 1] != t) g_seg_end[t] = i + 1;
}

// ---------------------------------------------------------------------------
__device__ __forceinline__ uint32_t smem_to_u32(const void* p) {
    uint32_t a;
    asm("{ .reg .u64 t; cvta.to.shared.u64 t, %1; cvt.u32.u64 %0, t; }"
        : "=r"(a) : "l"(p));
    return a;
}
__device__ __forceinline__ void ldsm_x4(uint32_t* r, uint32_t addr) {
    asm volatile("ldmatrix.sync.aligned.m8n8.x4.shared.b16 {%0,%1,%2,%3}, [%4];"
                 : "=r"(r[0]), "=r"(r[1]), "=r"(r[2]), "=r"(r[3]) : "r"(addr));
}
__device__ __forceinline__ void ldsm_x2(uint32_t& r0, uint32_t& r1, uint32_t addr) {
    asm volatile("ldmatrix.sync.aligned.m8n8.x2.shared.b16 {%0,%1}, [%2];"
                 : "=r"(r0), "=r"(r1) : "r"(addr));
}
__device__ __forceinline__ void hmma16816(float& c0, float& c1, float& c2, float& c3,
                                          uint32_t a0, uint32_t a1, uint32_t a2, uint32_t a3,
                                          uint32_t b0, uint32_t b1) {
    asm volatile(
        "mma.sync.aligned.m16n8k16.row.col.f32.bf16.bf16.f32 "
        "{%0,%1,%2,%3}, {%4,%5,%6,%7}, {%8,%9}, {%0,%1,%2,%3};"
        : "+f"(c0), "+f"(c1), "+f"(c2), "+f"(c3)
        : "r"(a0), "r"(a1), "r"(a2), "r"(a3), "r"(b0), "r"(b1));
}

// ---------------------------------------------------------------------------
// Split-bf16 GEMM, deduplicated fragments:
//   tok = th + tl, W = wh + wl;  out = th*wh + th*wl + tl*wh  (drop tl*wl).
// Token tile k-layout [0:32)=th, [32:64)=tl; W tile [0:32)=wh, [32:64)=wl.
//
// Column pairing: within each 16-col H group, n-tile "e" covers physical cols
// {4q, 4q+1} and "o" covers {4q+2, 4q+3} (q = lane&3) -> STG.128 per row.
// W staging permutes: phys col p -> row g*16 + ((p>>1)&1)*8 + 2*(p>>2) + (p&1).
//
// 1024 threads / 32 warps, each warp owns ONE 16-col H group -> breg = 16 regs,
// <=64 regs/thread, occupancy 32 warps/SM.
//
// smem rows 72 bf16 = 144 B (36 words): 8-row ldmatrix sets conflict-free.
static constexpr int TILE_TOK = 128;
static constexpr int ROWB     = 144;                 // bytes per k-row
static constexpr int SW_OFF   = 0;                   // W-split: 512 rows
static constexpr int ST0      = 512 * ROWB;          // 73728
static constexpr int TBYTES   = TILE_TOK * ROWB;     // 18432
static constexpr int ST1      = ST0 + TBYTES;        // 92160
static constexpr int SMEM_TOTAL = ST1 + TBYTES;      // 110592

#define NTHREADS 1024   // 32 warps

__global__ __launch_bounds__(NTHREADS, 1) void fused_hmma_kernel(
    const float* __restrict__ features,   // [S, 32]
    const float* __restrict__ W,          // [32, 512]
    const float* __restrict__ b,          // [512]
    float* __restrict__ out,              // [T, 512]
    int T, int ntiles)
{
    extern __shared__ char smem[];
    const uint32_t smem_base = smem_to_u32(smem);
    const int tid  = threadIdx.x;
    const int wid  = tid >> 5;            // 0..31
    const int lane = tid & 31;

    // --- Stage W^T split into smem with column-pair permutation (once) ---
    for (int idx = tid; idx < 32 * 512; idx += NTHREADS) {
        const int f = idx >> 9, h = idx & 511;       // coalesced LDG over h
        const float wv = W[idx];
        const __nv_bfloat16 hb = __float2bfloat16(wv);
        const __nv_bfloat16 lb = __float2bfloat16(wv - __bfloat162float(hb));
        const int g = h >> 4, p = h & 15;
        const int row = g * 16 + ((p >> 1) & 1) * 8 + 2 * (p >> 2) + (p & 1);
        char* r = smem + SW_OFF + row * ROWB;
        *(__nv_bfloat16*)(r + 2 * f)        = hb;    // wh  (k = f)
        *(__nv_bfloat16*)(r + 2 * (32 + f)) = lb;    // wl  (k = 32+f)
    }
    __syncthreads();

    // --- Hoist W fragments: 2 tiles (e/o) x 4 k-steps x 2 regs = 16 regs ---
    const int wsl = wid * 16;             // global H base of this warp
    uint32_t breg[2][4][2];
    {
        const uint32_t wb = smem_base + SW_OFF;
        #pragma unroll
        for (int eo = 0; eo < 2; eo++)
            #pragma unroll
            for (int ks = 0; ks < 4; ks++) {
                uint32_t addr = wb + (wsl + eo * 8 + (lane & 7)) * ROWB
                              + (ks * 16 + ((lane >> 3) & 1) * 8) * 2;
                ldsm_x2(breg[eo][ks][0], breg[eo][ks][1], addr);
            }
    }
    // Bias: thread's 4 consecutive output cols.
    const int q = lane & 3;
    const float4 bias4 = *reinterpret_cast<const float4*>(b + wsl + 4 * q);

    int tile = blockIdx.x;
    if (tile >= ntiles) return;   // grid is clamped; defensive (uniform per CTA)

    // --- Gather: thread (f = lane, token row base = wid) ---
    const int f = lane, trow = wid;
    float ts[4];
    auto gather = [&](int tile_) {
        const int tok0 = tile_ * TILE_TOK;
        #pragma unroll
        for (int j = 0; j < 4; j++) {
            const int tok = tok0 + trow + 32 * j;
            int s0 = 0, n = 0;
            if (tok < T) { s0 = g_seg_start[tok]; n = g_seg_end[tok] - s0; }
            const float* p = features + (size_t)s0 * 32 + f;
            float a0 = (n > 0) ? p[0]  : 0.0f;
            float a1 = (n > 1) ? p[32] : 0.0f;
            float a2 = (n > 2) ? p[64] : 0.0f;
            float ex = 0.0f;
            for (int si = 3; si < n; si++) ex += p[32 * si];
            ts[j] = 1e-10f + ((a0 + a1) + (a2 + ex));
        }
    };
    auto convert_sts = [&](char* B) {
        #pragma unroll
        for (int j = 0; j < 4; j++) {
            const int r = trow + 32 * j;
            const __nv_bfloat16 hb = __float2bfloat16(ts[j]);
            const __nv_bfloat16 lb =
                __float2bfloat16(ts[j] - __bfloat162float(hb));
            char* row = B + r * ROWB;
            *(__nv_bfloat16*)(row + 2 * f)        = hb;  // th (k = f)
            *(__nv_bfloat16*)(row + 2 * (32 + f)) = lb;  // tl (k = 32+f)
        }
    };

    // Prime the pipeline.
    gather(tile);
    convert_sts(smem + ST0);
    __syncthreads();

    int buf = 0;
    while (true) {
        const int next = tile + gridDim.x;
        const bool has_next = next < ntiles;

        // Prefetch next tile's gather LDGs (consumed after the MMA phase).
        if (has_next) gather(next);

        // --- MMA + store phase on current buffer ---
        const uint32_t cur = smem_base + (buf ? ST1 : ST0);
        const int tok0 = tile * TILE_TOK;
        const uint32_t arow0 = cur + (lane & 15) * ROWB + ((lane >> 4) * 8) * 2;

        #pragma unroll 1
        for (int m = 0; m < 8; m++) {
            const uint32_t arow = arow0 + m * 16 * ROWB;

            float e0 = bias4.x, e1 = bias4.y, e2 = e0, e3 = e1;
            float o0 = bias4.z, o1 = bias4.w, o2 = o0, o3 = o1;

            // th fragments (k = 0:32): th*wh, th*wl for both n-tiles.
            {
                uint32_t a0[4], a1[4];
                ldsm_x4(a0, arow);
                ldsm_x4(a1, arow + 32);
                hmma16816(e0, e1, e2, e3, a0[0], a0[1], a0[2], a0[3],
                          breg[0][0][0], breg[0][0][1]);
                hmma16816(e0, e1, e2, e3, a1[0], a1[1], a1[2], a1[3],
                          breg[0][1][0], breg[0][1][1]);
                hmma16816(e0, e1, e2, e3, a0[0], a0[1], a0[2], a0[3],
                          breg[0][2][0], breg[0][2][1]);
                hmma16816(e0, e1, e2, e3, a1[0], a1[1], a1[2], a1[3],
                          breg[0][3][0], breg[0][3][1]);
                hmma16816(o0, o1, o2, o3, a0[0], a0[1], a0[2], a0[3],
                          breg[1][0][0], breg[1][0][1]);
                hmma16816(o0, o1, o2, o3, a1[0], a1[1], a1[2], a1[3],
                          breg[1][1][0], breg[1][1][1]);
                hmma16816(o0, o1, o2, o3, a0[0], a0[1], a0[2], a0[3],
                          breg[1][2][0], breg[1][2][1]);
                hmma16816(o0, o1, o2, o3, a1[0], a1[1], a1[2], a1[3],
                          breg[1][3][0], breg[1][3][1]);
            }
            // tl fragments (k = 32:64): tl*wh for both n-tiles.
            {
                uint32_t a2[4], a3[4];
                ldsm_x4(a2, arow + 64);
                ldsm_x4(a3, arow + 96);
                hmma16816(e0, e1, e2, e3, a2[0], a2[1], a2[2], a2[3],
                          breg[0][0][0], breg[0][0][1]);
                hmma16816(e0, e1, e2, e3, a3[0], a3[1], a3[2], a3[3],
                          breg[0][1][0], breg[0][1][1]);
                hmma16816(o0, o1, o2, o3, a2[0], a2[1], a2[2], a2[3],
                          breg[1][0][0], breg[1][0][1]);
                hmma16816(o0, o1, o2, o3, a3[0], a3[1], a3[2], a3[3],
                          breg[1][1][0], breg[1][1][1]);
            }

            // 4 consecutive cols -> one STG.128 per row.
            const int r0 = tok0 + m * 16 + (lane >> 2);
            float* o = out + (size_t)r0 * 512 + wsl + 4 * q;
            if (r0 < T)
                *reinterpret_cast<float4*>(o) = make_float4(e0, e1, o0, o1);
            if (r0 + 8 < T)
                *reinterpret_cast<float4*>(o + 8 * 512) =
                    make_float4(e2, e3, o2, o3);
        }

        // Write next tile's token buffer; one sync per tile.
        if (has_next) convert_sts(smem + (buf ? ST0 : ST1));
        __syncthreads();
        if (!has_next) break;
        tile = next;
        buf ^= 1;
    }
}

// ---------------------------------------------------------------------------
extern "C" void kernel_launch(void* const* d_in, const int* in_sizes, int n_in,
                              void* d_out, int out_size) {
    const float* features = (const float*)d_in[0];   // [S, 32]
    const float* W        = (const float*)d_in[1];   // [32, 512]
    const float* b        = (const float*)d_in[2];   // [512]
    const int*   idx      = (const int*)d_in[3];     // [S]
    float*       out      = (float*)d_out;           // [T, 512]

    const int S = in_sizes[3];
    const int T = out_size / 512;
    const int ntiles = (T + TILE_TOK - 1) / TILE_TOK;

    static int nsm = 0;
    if (nsm == 0) {
        // First call is the (non-captured) correctness run; cached afterwards.
        cudaDeviceGetAttribute(&nsm, cudaDevAttrMultiProcessorCount, 0);
        if (nsm <= 0) nsm = 148;
        cudaFuncSetAttribute(fused_hmma_kernel,
                             cudaFuncAttributeMaxDynamicSharedMemorySize,
                             SMEM_TOTAL);
    }

    seg_bounds_kernel<<<(S + 255) / 256, 256>>>(idx, S);

    int grid = nsm;
    if (grid > ntiles) grid = ntiles;
    fused_hmma_kernel<<<grid, NTHREADS, SMEM_TOTAL>>>(
        features, W, b, out, T, ntiles);
}